// round 14
// baseline (speedup 1.0000x reference)
#include <cuda_runtime.h>

#define NTYPES 20
#define LMAXC  13
#define DV     64
#define NRES_MAX 2048
#define B_MAX    16

__constant__ int c_res_len[NTYPES] = {3,4,5,5,6,6,6,7,7,7,7,7,8,8,8,9,10,10,11,13};

__device__ int g_starts[NRES_MAX];     // atom start per residue
__device__ int g_rowstart[NRES_MAX];   // first output-row per residue
// packed: i (bits 0..10) | m (bits 11..14) | start (bits 15..28)
__device__ int g_rowmap[NRES_MAX * (LMAXC + 1)];

// ---------------------------------------------------------------------------
// Setup: two warp-shuffle scans only (~5 us measured).
// ---------------------------------------------------------------------------
__device__ __forceinline__ int block_excl_scan_pair(int my, int tid, int* wsum) {
    const int lane = tid & 31, wid = tid >> 5;
    int s = my;
#pragma unroll
    for (int o = 1; o < 32; o <<= 1) {
        int n = __shfl_up_sync(~0u, s, o);
        if (lane >= o) s += n;
    }
    if (lane == 31) wsum[wid] = s;
    __syncthreads();
    if (wid == 0) {
        int t = wsum[lane];
#pragma unroll
        for (int o = 1; o < 32; o <<= 1) {
            int n = __shfl_up_sync(~0u, t, o);
            if (lane >= o) t += n;
        }
        wsum[lane] = t;
    }
    __syncthreads();
    int base = ((wid > 0) ? wsum[wid - 1] : 0) + (s - my);
    __syncthreads();
    return base;
}

__global__ void setup_kernel(const int* __restrict__ seq, int nres) {
    __shared__ int wsum[32];
    __shared__ int slen[NTYPES];
    const int tid = threadIdx.x;
    if (tid < NTYPES) slen[tid] = c_res_len[tid];
    __syncthreads();

    const int j0 = 2 * tid, j1 = 2 * tid + 1;
    const int l0 = (j0 < nres) ? slen[seq[j0]] : 0;
    const int l1 = (j1 < nres) ? slen[seq[j1]] : 0;

    const int base = block_excl_scan_pair(l0 + l1, tid, wsum);
    if (j0 < nres) g_starts[j0] = base;
    if (j1 < nres) g_starts[j1] = base + l0;

    const int r0 = (j0 < nres) ? l0 + 1 : 0;
    const int r1 = (j1 < nres) ? l1 + 1 : 0;
    const int rbase = block_excl_scan_pair(r0 + r1, tid, wsum);
    if (j0 < nres) g_rowstart[j0] = rbase;
    if (j1 < nres) g_rowstart[j1] = rbase + r0;
}

// ---------------------------------------------------------------------------
// Rowmap fill: one thread per residue, multi-block (~2 us).
// ---------------------------------------------------------------------------
__global__ void fill_rowmap(const int* __restrict__ seq, int nres) {
    const int i = blockIdx.x * 256 + threadIdx.x;
    if (i >= nres) return;
    const int L = c_res_len[seq[i]];
    const int rs = g_rowstart[i];
    const int rec = i | (g_starts[i] << 15);
#pragma unroll 4
    for (int m = 0; m <= L; ++m) g_rowmap[rs + m] = rec | (m << 11);
}

// ---------------------------------------------------------------------------
// Main kernel (R5 hot loop; epilogue = STG.64 + STG.32 per thread)
// ---------------------------------------------------------------------------
#define PACK_DUP(dst, w) \
    asm("mov.b64 %0, {%1, %2};" : "=l"(dst) : "r"(__float_as_uint(w)), "r"(__float_as_uint(w)))
#define FMA2(acc, x, y) \
    asm("fma.rn.f32x2 %0, %1, %2, %3;" : "=l"(acc) : "l"(x), "l"(y), "l"(acc))
#define ADD2(dst, x, y) \
    asm("add.rn.f32x2 %0, %1, %2;" : "=l"(dst) : "l"(x), "l"(y))
#define UNPACK2(lo, hi, src) \
    asm("mov.b64 {%0, %1}, %2;" : "=r"(lo), "=r"(hi) : "l"(src))
#define PACK2U(dst, a, b) \
    asm("mov.b64 %0, {%1, %2};" : "=l"(dst) : "r"(a), "r"(b))
#define LDS_V2U64(x, y, addr) \
    asm volatile("ld.shared.v2.u64 {%0, %1}, [%2];" : "=l"(x), "=l"(y) : "r"(addr))

__device__ __forceinline__ unsigned smem_u32(const void* p) {
    unsigned r;
    asm("{ .reg .u64 t; cvta.to.shared.u64 t, %1; cvt.u32.u64 %0, t; }" : "=r"(r) : "l"(p));
    return r;
}

template <int L>
__device__ __forceinline__ void batch_loop(
    int B, bool active, bool even, unsigned cur,
    const float* __restrict__ wr,
    float* opA, float* opB, long ostride)   // opA 8B-aligned (STG.64), opB (STG.32)
{
    unsigned long long ww[L];
#pragma unroll
    for (int l = 0; l < L; ++l) {
        const float w = __ldg(wr + l);
        PACK_DUP(ww[l], w);
    }

#pragma unroll 2
    for (int b = 0; b < B; ++b) {
        unsigned long long aA = 0ull, aB = 0ull, cA = 0ull, cB = 0ull;
#pragma unroll
        for (int l = 0; l < L; ++l) {
            unsigned long long d01, d2p;
            LDS_V2U64(d01, d2p, cur + l * 16);
            if (l & 1) { FMA2(aB, ww[l], d01); FMA2(cB, ww[l], d2p); }
            else       { FMA2(aA, ww[l], d01); FMA2(cA, ww[l], d2p); }
        }
        unsigned long long a01, a2p;
        ADD2(a01, aA, aB);
        ADD2(a2p, cA, cB);
        if (active) {
            unsigned u0, u1, u2, u3;
            UNPACK2(u0, u1, a01);     // u0 = out[0], u1 = out[1]
            UNPACK2(u2, u3, a2p);     // u2 = out[2]
            // even v: 64-bit (u0,u1) @ op, 32-bit u2 @ op+2
            // odd  v: 64-bit (u1,u2) @ op+1, 32-bit u0 @ op
            unsigned long long s64;
            if (even) s64 = a01; else PACK2U(s64, u1, u2);
            const unsigned s32 = even ? u2 : u0;
            *reinterpret_cast<unsigned long long*>(opA) = s64;
            *reinterpret_cast<unsigned*>(opB) = s32;
        }
        opA += ostride;
        opB += ostride;
        cur += 224u;   // 56 floats per batch
    }
}

__global__ __launch_bounds__(256) void posmix_kernel(
    const float* __restrict__ pos_atm, const float* __restrict__ pos_amn,
    const float* __restrict__ W_amn,  const float* __restrict__ W_atm,
    const int* __restrict__ seq,
    int B, int nres, int atoms, int totrows, float* __restrict__ out)
{
    __shared__ float sdif[4 * B_MAX * 56];   // 14336 B: (slot, b, l, 4)

    const int tid  = threadIdx.x;
    const int slot = tid >> 6;
    const int v    = tid & 63;
    const int row  = blockIdx.x * 4 + slot;
    const bool active = (row < totrows);
    const int rowc = active ? row : (totrows - 1);

    const int rm    = g_rowmap[rowc];          // warp-uniform single load
    const int i     = rm & 2047;
    const int m     = (rm >> 11) & 15;
    const int start = rm >> 15;
    const int t     = seq[i];
    const int L     = c_res_len[t];
    const bool is_amn = (m == L);

    // --- compute diffs for this slot's residue, all batches, into smem ---
    if (v < 3 * L) {
        const int l = v / 3;
        const int d = v - 3 * l;
        const float* paP = pos_atm + (size_t)start * 3 + v;
        const float* pnP = pos_amn + (size_t)i * 3 + d;
        float* sd = sdif + slot * (B_MAX * 56) + l * 4 + d;
        const long astr = (long)atoms * 3;
        const long nstr = (long)nres * 3;
#pragma unroll 4
        for (int b = 0; b < B; ++b)
            sd[b * 56] = paP[b * astr] - pnP[b * nstr];
    }

    // weight row for this (m, v)
    const float* wr = is_amn
        ? (W_amn + ((size_t)t * DV + v) * LMAXC)
        : (W_atm + (((size_t)t * LMAXC + m) * DV + v) * LMAXC);

    size_t base; long ostride;
    if (is_amn) {
        base    = (size_t)B * atoms * 192 + ((size_t)i * DV + v) * 3;
        ostride = (long)nres * 192;
    } else {
        base    = ((size_t)(start + m) * DV + v) * 3;
        ostride = (long)atoms * 192;
    }
    float* op = out + base;
    const bool even = ((v & 1) == 0);
    float* opA = op + (even ? 0 : 1);    // 8B-aligned 64-bit store target
    float* opB = op + (even ? 2 : 0);    // 32-bit store target

    __syncthreads();

    const unsigned cur = smem_u32(sdif) + (unsigned)(slot * (B_MAX * 56)) * 4u;

    switch (L) {
        case  3: batch_loop< 3>(B, active, even, cur, wr, opA, opB, ostride); break;
        case  4: batch_loop< 4>(B, active, even, cur, wr, opA, opB, ostride); break;
        case  5: batch_loop< 5>(B, active, even, cur, wr, opA, opB, ostride); break;
        case  6: batch_loop< 6>(B, active, even, cur, wr, opA, opB, ostride); break;
        case  7: batch_loop< 7>(B, active, even, cur, wr, opA, opB, ostride); break;
        case  8: batch_loop< 8>(B, active, even, cur, wr, opA, opB, ostride); break;
        case  9: batch_loop< 9>(B, active, even, cur, wr, opA, opB, ostride); break;
        case 10: batch_loop<10>(B, active, even, cur, wr, opA, opB, ostride); break;
        case 11: batch_loop<11>(B, active, even, cur, wr, opA, opB, ostride); break;
        default: batch_loop<13>(B, active, even, cur, wr, opA, opB, ostride); break;
    }
}

// ---------------------------------------------------------------------------
extern "C" void kernel_launch(void* const* d_in, const int* in_sizes, int n_in,
                              void* d_out, int out_size) {
    const float* pos_atm = (const float*)d_in[0];
    const float* pos_amn = (const float*)d_in[1];
    const float* W_amn   = (const float*)d_in[2];
    const float* W_atm   = (const float*)d_in[3];
    const int*   seq     = (const int*)d_in[4];

    const int nres  = in_sizes[4];
    const int B     = in_sizes[1] / (nres * 3);
    const int atoms = in_sizes[0] / (B * 3);
    const int totrows = atoms + nres;   // sum over residues of (L+1)

    setup_kernel<<<1, 1024>>>(seq, nres);
    fill_rowmap<<<(nres + 255) / 256, 256>>>(seq, nres);
    const int nblocks = (totrows + 3) / 4;
    posmix_kernel<<<nblocks, 256>>>(pos_atm, pos_amn, W_amn, W_atm, seq,
                                    B, nres, atoms, totrows, (float*)d_out);
}